// round 1
// baseline (speedup 1.0000x reference)
#include <cuda_runtime.h>
#include <cstdint>

// Problem constants (fixed shapes from setup_inputs)
#define BS      32
#define TT      50
#define HH      104
#define WW      104
#define HWP     (HH*WW)          // 10816
#define AA      3
#define CH      75               // 3 * 25
#define NC      20               // NUM_CLASSES - 1
#define NCELLS  (BS*AA*HWP)      // 1,038,336
#define NVEC    (NCELLS/4)       // 259,584
#define VEC_PER_PLANE (HWP/4)    // 2704
#define NBW     ((NCELLS+31)/32) // 32,448 bitfield words

// Scratch (device globals; no allocations allowed)
__device__ int      g_owner[NCELLS];
__device__ unsigned g_tcls[NCELLS];
__device__ unsigned g_nbits[NBW];
__device__ int      g_nlist[4800];
__device__ int      g_ncount;
__device__ int      g_npos;
__device__ double   g_acc[6];     // sx, sy, sw, sh, sobj1, scls
__device__ double   g_obj2;       // dense softplus sum (before subtraction)

__constant__ float c_saw[3] = {14.5f, 19.5f, 46.625f};   // ANCHORS / 8
__constant__ float c_sah[3] = {11.25f, 24.75f, 40.75f};

// -log(1 - sigmoid(z)) clipped like the reference
__device__ __forceinline__ float sp_fast(float z) {
    float s = __logf(1.0f + __expf(z));
    s = fminf(s, 100.0f);
    if (z > 16.6f) s = 100.0f;   // fp32 sigmoid rounds to 1 -> ref clips at 100
    return s;
}

__device__ __forceinline__ float sigmoid_ref(float z) {
    if (z >= 0.0f) return 1.0f / (1.0f + expf(-z));
    float e = expf(z);
    return e / (1.0f + e);
}

__device__ __forceinline__ float bce_ref(float p, float t) {
    float lp  = fmaxf(logf(p), -100.0f);
    float l1p = fmaxf(logf(1.0f - p), -100.0f);
    return -(t * lp + (1.0f - t) * l1p);
}

struct Tgt {
    bool  valid;
    int   gi, gj, bn, cls;
    float tx, ty, tw, th;
    float iou[3];
};

__device__ __forceinline__ void compute_target(const float* __restrict__ tg,
                                               int b, int t, Tgt& o) {
    const float* p = tg + ((size_t)b * TT + t) * 5;
    float cx = p[0], cy = p[1], w = p[2], h = p[3], cl = p[4];
    o.valid = (cx + cy + w + h + cl) > 0.0f;
    float gx = cx * (float)WW, gy = cy * (float)HH;
    float gw = w  * (float)WW, gh = h  * (float)HH;
    o.gi = (int)gx;  o.gj = (int)gy;
    float best = -1.0f; int bn = 0;
    #pragma unroll
    for (int a = 0; a < 3; a++) {
        float aw = c_saw[a], ah = c_sah[a];
        float inter = fmaxf(fminf(gw, aw) + 1.0f, 0.0f) *
                      fmaxf(fminf(gh, ah) + 1.0f, 0.0f);
        float area_g = (gw + 1.0f) * (gh + 1.0f);
        float area_a = (aw + 1.0f) * (ah + 1.0f);
        float iou = inter / (area_g + area_a - inter + 1e-16f);
        o.iou[a] = iou;
        if (iou > best) { best = iou; bn = a; }
    }
    o.bn = bn;
    o.tx = gx - (float)o.gi;
    o.ty = gy - (float)o.gj;
    o.tw = logf(gw / c_saw[bn] + 1e-16f);
    o.th = logf(gh / c_sah[bn] + 1e-16f);
    o.cls = (int)cl;
}

// ---------------- Kernel 0: init scratch ----------------
__global__ void k_init() {
    int i = blockIdx.x * blockDim.x + threadIdx.x;
    int stride = gridDim.x * blockDim.x;
    for (int k = i; k < NCELLS; k += stride) { g_owner[k] = -1; g_tcls[k] = 0u; }
    for (int k = i; k < NBW; k += stride) g_nbits[k] = 0u;
    if (i == 0) {
        g_ncount = 0; g_npos = 0; g_obj2 = 0.0;
        #pragma unroll
        for (int k = 0; k < 6; k++) g_acc[k] = 0.0;
    }
}

// ---------------- Kernel 1: target prep (1600 threads) ----------------
__global__ void k_prep(const float* __restrict__ tg) {
    int idx = blockIdx.x * blockDim.x + threadIdx.x;
    if (idx >= BS * TT) return;
    int b = idx / TT, t = idx % TT;
    Tgt o;
    compute_target(tg, b, t, o);
    if (!o.valid) return;
    if (o.gi < 0 || o.gi >= WW || o.gj < 0 || o.gj >= HH) return;  // drop-mode
    int cell = ((b * AA + o.bn) * HH + o.gj) * WW + o.gi;
    atomicMax(&g_owner[cell], idx);
    atomicOr(&g_tcls[cell], 1u << o.cls);
    #pragma unroll
    for (int a = 0; a < 3; a++) {
        if (o.iou[a] > 0.5f) {
            int nc = ((b * AA + a) * HH + o.gj) * WW + o.gi;
            unsigned m = 1u << (nc & 31);
            unsigned old = atomicOr(&g_nbits[nc >> 5], m);
            if (!(old & m)) {
                int k = atomicAdd(&g_ncount, 1);
                g_nlist[k] = nc;
            }
        }
    }
}

// ---------------- Kernel 2: dense conf reduction ----------------
__global__ void k_dense(const float* __restrict__ inp) {
    int v = blockIdx.x * blockDim.x + threadIdx.x;
    float local = 0.0f;
    if (v < NVEC) {
        int plane = v / VEC_PER_PLANE;       // 0..95
        int off   = (v - plane * VEC_PER_PLANE) * 4;
        int b = plane / AA, a = plane - b * AA;
        const float4* p = (const float4*)(inp +
            ((size_t)(b * CH + a * 25 + 4)) * HWP + off);
        float4 z = *p;
        local = sp_fast(z.x) + sp_fast(z.y) + sp_fast(z.z) + sp_fast(z.w);
    }
    // block reduce
    #pragma unroll
    for (int o = 16; o > 0; o >>= 1)
        local += __shfl_down_sync(0xFFFFFFFFu, local, o);
    __shared__ float ws[8];
    int lane = threadIdx.x & 31, wid = threadIdx.x >> 5;
    if (lane == 0) ws[wid] = local;
    __syncthreads();
    if (wid == 0) {
        float v2 = (lane < (blockDim.x >> 5)) ? ws[lane] : 0.0f;
        #pragma unroll
        for (int o = 4; o > 0; o >>= 1)
            v2 += __shfl_down_sync(0xFFFFFFFFu, v2, o);
        if (lane == 0) atomicAdd(&g_obj2, (double)v2);
    }
}

// ---------------- Kernel 3: sparse corrections ----------------
__global__ void k_sparse(const float* __restrict__ inp,
                         const float* __restrict__ tg) {
    int idx = blockIdx.x * blockDim.x + threadIdx.x;
    if (idx < BS * TT) {
        // mask-cell path
        int b = idx / TT, t = idx % TT;
        Tgt o;
        compute_target(tg, b, t, o);
        if (!o.valid) return;
        if (o.gi < 0 || o.gi >= WW || o.gj < 0 || o.gj >= HH) return;
        int cell = ((b * AA + o.bn) * HH + o.gj) * WW + o.gi;
        if (g_owner[cell] != idx) return;    // collision loser
        const float* base = inp + ((size_t)(b * CH + o.bn * 25)) * HWP
                                + o.gj * WW + o.gi;
        float zx = base[0],        zy = base[HWP];
        float zw = base[2 * HWP],  zh = base[3 * HWP];
        float zc = base[4 * HWP];
        float px = sigmoid_ref(zx), py = sigmoid_ref(zy), pc = sigmoid_ref(zc);
        atomicAdd(&g_acc[0], (double)bce_ref(px, o.tx));
        atomicAdd(&g_acc[1], (double)bce_ref(py, o.ty));
        float dw = zw - o.tw, dh = zh - o.th;
        atomicAdd(&g_acc[2], (double)(dw * dw));
        atomicAdd(&g_acc[3], (double)(dh * dh));
        atomicAdd(&g_acc[4], (double)(-fmaxf(logf(pc), -100.0f)));
        unsigned bits = g_tcls[cell];
        float cs = 0.0f;
        #pragma unroll
        for (int c = 0; c < NC; c++) {
            float z = base[(size_t)(5 + c) * HWP];
            float p = sigmoid_ref(z);
            float tv = (float)((bits >> c) & 1u);
            cs += bce_ref(p, tv);
        }
        atomicAdd(&g_acc[5], (double)cs);
        atomicAdd(&g_npos, 1);
    } else {
        // noobj-zero subtraction path
        int j = idx - BS * TT;
        if (j >= g_ncount) return;
        int nc = g_nlist[j];
        int plane = nc / HWP, off = nc - plane * HWP;
        int b = plane / AA, a = plane - b * AA;
        float z = inp[((size_t)(b * CH + a * 25 + 4)) * HWP + off];
        atomicAdd(&g_obj2, -(double)sp_fast(z));
    }
}

// ---------------- Kernel 4: finalize ----------------
__global__ void k_fin(float* __restrict__ out) {
    if (threadIdx.x == 0 && blockIdx.x == 0) {
        const double N = (double)NCELLS;
        out[0] = (float)(g_acc[0] / N * 2.5);
        out[1] = (float)(g_acc[1] / N * 2.5);
        out[2] = (float)(g_acc[2] / N * 2.5);
        out[3] = (float)(g_acc[3] / N * 2.5);
        out[4] = (float)(g_acc[4] / N + 0.5 * g_obj2 / N);
        double dn = (double)g_npos * (double)NC;
        if (dn < 1.0) dn = 1.0;
        out[5] = (float)(g_acc[5] / dn);
    }
}

extern "C" void kernel_launch(void* const* d_in, const int* in_sizes, int n_in,
                              void* d_out, int out_size) {
    const float* a0 = (const float*)d_in[0];
    const float* a1 = (const float*)d_in[1];
    const float* inp;
    const float* tg;
    if (in_sizes[0] == BS * TT * 5) { tg = a0; inp = a1; }
    else                            { inp = a0; tg = a1; }

    k_init<<<512, 256>>>();
    k_prep<<<(BS * TT + 255) / 256, 256>>>(tg);
    k_dense<<<(NVEC + 255) / 256, 256>>>(inp);
    k_sparse<<<(BS * TT + 4800 + 255) / 256, 256>>>(inp, tg);
    k_fin<<<1, 32>>>((float*)d_out);
}

// round 4
// speedup vs baseline: 1.2397x; 1.2397x over previous
#include <cuda_runtime.h>
#include <cstdint>

// Fixed shapes from setup_inputs
#define BS      32
#define TT      50
#define HH      104
#define WW      104
#define HWP     (HH*WW)          // 10816
#define AA      3
#define CH      75               // 3 * 25
#define NC      20               // NUM_CLASSES - 1
#define NCELLS  (BS*AA*HWP)      // 1,038,336
#define NVEC    (NCELLS/4)       // 259,584
#define VEC_PER_PLANE (HWP/4)    // 2704

// Small scratch only (counters + accumulators)
__device__ double g_acc[6];      // sx, sy, sw, sh, sobj1, scls
__device__ double g_obj2;        // dense softplus sum (noobj subtractions applied here)
__device__ int    g_npos;

__constant__ float c_saw[3] = {14.5f, 19.5f, 46.625f};   // ANCHORS / 8
__constant__ float c_sah[3] = {11.25f, 24.75f, 40.75f};

// -log(1 - sigmoid(z)) clipped like the reference
__device__ __forceinline__ float sp_fast(float z) {
    float s = __logf(1.0f + __expf(z));
    s = fminf(s, 100.0f);
    if (z > 16.6f) s = 100.0f;   // fp32 sigmoid rounds to 1 -> ref clips log at -100
    return s;
}

__device__ __forceinline__ float sigmoid_ref(float z) {
    if (z >= 0.0f) return 1.0f / (1.0f + expf(-z));
    float e = expf(z);
    return e / (1.0f + e);
}

__device__ __forceinline__ float bce_ref(float p, float t) {
    float lp  = fmaxf(logf(p), -100.0f);
    float l1p = fmaxf(logf(1.0f - p), -100.0f);
    return -(t * lp + (1.0f - t) * l1p);
}

struct TgtL {
    bool  valid;
    int   gi, gj, bn, cls;
    float gx, gy, gw, gh;
    float iou0, iou1, iou2;
};

__device__ __forceinline__ void light_target(const float* __restrict__ tg,
                                             int b, int t, TgtL& o) {
    const float* p = tg + ((size_t)b * TT + t) * 5;
    float cx = p[0], cy = p[1], w = p[2], h = p[3], cl = p[4];
    o.valid = (cx + cy + w + h + cl) > 0.0f;
    o.gx = cx * (float)WW;  o.gy = cy * (float)HH;
    o.gw = w  * (float)WW;  o.gh = h  * (float)HH;
    o.gi = (int)o.gx;       o.gj = (int)o.gy;
    float ious[3];
    float best = -1.0f; int bn = 0;
    #pragma unroll
    for (int a = 0; a < 3; a++) {
        float aw = c_saw[a], ah = c_sah[a];
        float inter = fmaxf(fminf(o.gw, aw) + 1.0f, 0.0f) *
                      fmaxf(fminf(o.gh, ah) + 1.0f, 0.0f);
        float area_g = (o.gw + 1.0f) * (o.gh + 1.0f);
        float area_a = (aw + 1.0f) * (ah + 1.0f);
        float iou = inter / (area_g + area_a - inter + 1e-16f);
        ious[a] = iou;
        if (iou > best) { best = iou; bn = a; }
    }
    o.iou0 = ious[0]; o.iou1 = ious[1]; o.iou2 = ious[2];
    o.bn = bn;
    o.cls = (int)cl;
}

__device__ __forceinline__ float get_iou(const TgtL& o, int a) {
    return a == 0 ? o.iou0 : (a == 1 ? o.iou1 : o.iou2);
}

// ---------------- Kernel 0: tiny init ----------------
__global__ void k_init0() {
    if (threadIdx.x == 0) {
        g_obj2 = 0.0; g_npos = 0;
        #pragma unroll
        for (int k = 0; k < 6; k++) g_acc[k] = 0.0;
    }
}

// ---------------- Kernel 1: dense conf reduction ----------------
__global__ void k_dense(const float* __restrict__ inp) {
    int v = blockIdx.x * blockDim.x + threadIdx.x;
    float local = 0.0f;
    if (v < NVEC) {
        int plane = v / VEC_PER_PLANE;       // 0..95
        int off   = (v - plane * VEC_PER_PLANE) * 4;
        int b = plane / AA, a = plane - b * AA;
        const float4* p = (const float4*)(inp +
            ((size_t)(b * CH + a * 25 + 4)) * HWP + off);
        float4 z = *p;
        local = sp_fast(z.x) + sp_fast(z.y) + sp_fast(z.z) + sp_fast(z.w);
    }
    #pragma unroll
    for (int o = 16; o > 0; o >>= 1)
        local += __shfl_down_sync(0xFFFFFFFFu, local, o);
    __shared__ float ws[8];
    int lane = threadIdx.x & 31, wid = threadIdx.x >> 5;
    if (lane == 0) ws[wid] = local;
    __syncthreads();
    if (wid == 0) {
        float v2 = (lane < (blockDim.x >> 5)) ? ws[lane] : 0.0f;
        #pragma unroll
        for (int o = 4; o > 0; o >>= 1)
            v2 += __shfl_down_sync(0xFFFFFFFFu, v2, o);
        if (lane == 0) atomicAdd(&g_obj2, (double)v2);
    }
}

// ---------------- Kernel 2: warp-per-target sparse ----------------
__global__ void k_sparse2(const float* __restrict__ inp,
                          const float* __restrict__ tg) {
    int warp = (blockIdx.x * blockDim.x + threadIdx.x) >> 5;
    int lane = threadIdx.x & 31;
    if (warp >= BS * TT) return;
    int b = warp / TT, t = warp % TT;

    TgtL me;
    light_target(tg, b, t, me);
    if (!me.valid) return;
    if (me.gi < 0 || me.gi >= WW || me.gj < 0 || me.gj >= HH) return;

    // ---- in-warp scans over the 50 peer targets of this batch ----
    bool conflict = false;          // a later target claims same (bn,gj,gi)
    unsigned bits = 0u;             // OR of class bits of all claimants
    bool dup0 = false, dup1 = false, dup2 = false;  // earlier target claims noobj cell
    #pragma unroll
    for (int r = 0; r < 2; r++) {
        int t2 = lane + r * 32;
        TgtL o; o.valid = false;
        if (t2 < TT) light_target(tg, b, t2, o);
        bool inb = o.valid && o.gi >= 0 && o.gi < WW && o.gj >= 0 && o.gj < HH;
        bool mc  = inb && (o.gi == me.gi) && (o.gj == me.gj);
        bool mbn = mc && (o.bn == me.bn);
        if (__ballot_sync(0xFFFFFFFFu, mbn && (t2 > t))) conflict = true;
        unsigned bv = mbn ? (1u << o.cls) : 0u;
        #pragma unroll
        for (int s = 16; s > 0; s >>= 1)
            bv |= __shfl_xor_sync(0xFFFFFFFFu, bv, s);
        bits |= bv;
        if (__ballot_sync(0xFFFFFFFFu, mc && (o.iou0 > 0.5f) && (t2 < t))) dup0 = true;
        if (__ballot_sync(0xFFFFFFFFu, mc && (o.iou1 > 0.5f) && (t2 < t))) dup1 = true;
        if (__ballot_sync(0xFFFFFFFFu, mc && (o.iou2 > 0.5f) && (t2 < t))) dup2 = true;
    }

    // ---- mask-cell losses: lanes 0..24 load the 25 channel logits ----
    float tx = me.gx - (float)me.gi;
    float ty = me.gy - (float)me.gj;
    float v = 0.0f;
    const float* base = inp + ((size_t)(b * CH + me.bn * 25)) * HWP
                            + me.gj * WW + me.gi;
    if (!conflict && lane < 25) {
        float z = base[(size_t)lane * HWP];
        if (lane == 0) {
            v = bce_ref(sigmoid_ref(z), tx);
        } else if (lane == 1) {
            v = bce_ref(sigmoid_ref(z), ty);
        } else if (lane == 2) {
            float tw = logf(me.gw / c_saw[me.bn] + 1e-16f);
            float d = z - tw; v = d * d;
        } else if (lane == 3) {
            float th = logf(me.gh / c_sah[me.bn] + 1e-16f);
            float d = z - th; v = d * d;
        } else if (lane == 4) {
            v = -fmaxf(logf(sigmoid_ref(z)), -100.0f);
        } else {
            float tv = (float)((bits >> (lane - 5)) & 1u);
            v = bce_ref(sigmoid_ref(z), tv);
        }
    }

    // ---- noobj subtraction: lanes 25..27 handle anchors 0..2 ----
    float nsub = 0.0f;
    {
        int a = lane - 25;
        if (a >= 0 && a < 3) {
            bool dup = (a == 0) ? dup0 : (a == 1 ? dup1 : dup2);
            if (get_iou(me, a) > 0.5f && !dup) {
                float z = inp[((size_t)(b * CH + a * 25 + 4)) * HWP
                              + me.gj * WW + me.gi];
                nsub = sp_fast(z);
            }
        }
    }

    // ---- reductions ----
    float clsv = (lane >= 5 && lane < 25) ? v : 0.0f;
    #pragma unroll
    for (int s = 16; s > 0; s >>= 1) {
        clsv += __shfl_xor_sync(0xFFFFFFFFu, clsv, s);
        nsub += __shfl_xor_sync(0xFFFFFFFFu, nsub, s);
    }
    float v1 = __shfl_sync(0xFFFFFFFFu, v, 1);
    float v2 = __shfl_sync(0xFFFFFFFFu, v, 2);
    float v3 = __shfl_sync(0xFFFFFFFFu, v, 3);
    float v4 = __shfl_sync(0xFFFFFFFFu, v, 4);

    if (lane == 0) {
        if (nsub != 0.0f) atomicAdd(&g_obj2, -(double)nsub);
        if (!conflict) {
            atomicAdd(&g_acc[0], (double)v);
            atomicAdd(&g_acc[1], (double)v1);
            atomicAdd(&g_acc[2], (double)v2);
            atomicAdd(&g_acc[3], (double)v3);
            atomicAdd(&g_acc[4], (double)v4);
            atomicAdd(&g_acc[5], (double)clsv);
            atomicAdd(&g_npos, 1);
        }
    }
}

// ---------------- Kernel 3: finalize ----------------
__global__ void k_fin(float* __restrict__ out) {
    if (threadIdx.x == 0 && blockIdx.x == 0) {
        const double N = (double)NCELLS;
        out[0] = (float)(g_acc[0] / N * 2.5);
        out[1] = (float)(g_acc[1] / N * 2.5);
        out[2] = (float)(g_acc[2] / N * 2.5);
        out[3] = (float)(g_acc[3] / N * 2.5);
        out[4] = (float)(g_acc[4] / N + 0.5 * g_obj2 / N);
        double dn = (double)g_npos * (double)NC;
        if (dn < 1.0) dn = 1.0;
        out[5] = (float)(g_acc[5] / dn);
    }
}

extern "C" void kernel_launch(void* const* d_in, const int* in_sizes, int n_in,
                              void* d_out, int out_size) {
    const float* a0 = (const float*)d_in[0];
    const float* a1 = (const float*)d_in[1];
    const float* inp;
    const float* tg;
    if (in_sizes[0] == BS * TT * 5) { tg = a0; inp = a1; }
    else                            { inp = a0; tg = a1; }

    k_init0<<<1, 32>>>();
    k_dense<<<(NVEC + 255) / 256, 256>>>(inp);
    k_sparse2<<<(BS * TT * 32 + 255) / 256, 256>>>(inp, tg);
    k_fin<<<1, 32>>>((float*)d_out);
}

// round 8
// speedup vs baseline: 2.2246x; 1.7945x over previous
#include <cuda_runtime.h>
#include <cstdint>

// Fixed shapes from setup_inputs
#define BS      32
#define TT      50
#define HH      104
#define WW      104
#define HWP     (HH*WW)          // 10816
#define AA      3
#define CH      75               // 3 * 25
#define NC      20               // NUM_CLASSES - 1
#define NCELLS  (BS*AA*HWP)      // 1,038,336
#define NVEC    (NCELLS/4)       // 259,584
#define VEC_PER_PLANE (HWP/4)    // 2704

#define BLOCKS  507
#define THREADS 256
#define HALFV   (BLOCKS*THREADS) // 129,792 ; 2*HALFV == NVEC exactly

// Persistent scratch (zero-initialized at module load; every launch ends with
// these reset to zero by the finalizing block, so each graph replay starts clean)
__device__ double g_acc[6];      // sx, sy, sw, sh, sobj1, scls
__device__ double g_obj2;        // dense softplus sum minus noobj-zero cells
__device__ int    g_npos;
__device__ int    g_done;

__constant__ float c_saw[3] = {14.5f, 19.5f, 46.625f};   // ANCHORS / 8
__constant__ float c_sah[3] = {11.25f, 24.75f, 40.75f};

// -log(1 - sigmoid(z)) clipped like the reference
__device__ __forceinline__ float sp_fast(float z) {
    float s = __logf(1.0f + __expf(z));
    s = fminf(s, 100.0f);
    if (z > 16.6f) s = 100.0f;   // fp32 sigmoid rounds to 1 -> ref clips log at -100
    return s;
}

__device__ __forceinline__ float sigmoid_ref(float z) {
    if (z >= 0.0f) return 1.0f / (1.0f + expf(-z));
    float e = expf(z);
    return e / (1.0f + e);
}

__device__ __forceinline__ float bce_ref(float p, float t) {
    float lp  = fmaxf(logf(p), -100.0f);
    float l1p = fmaxf(logf(1.0f - p), -100.0f);
    return -(t * lp + (1.0f - t) * l1p);
}

struct TgtL {
    bool  valid;
    int   gi, gj, bn, cls;
    float gx, gy, gw, gh;
    float iou0, iou1, iou2;
};

__device__ __forceinline__ void light_target(const float* __restrict__ tg,
                                             int b, int t, TgtL& o) {
    const float* p = tg + ((size_t)b * TT + t) * 5;
    float cx = p[0], cy = p[1], w = p[2], h = p[3], cl = p[4];
    o.valid = (cx + cy + w + h + cl) > 0.0f;
    o.gx = cx * (float)WW;  o.gy = cy * (float)HH;
    o.gw = w  * (float)WW;  o.gh = h  * (float)HH;
    o.gi = (int)o.gx;       o.gj = (int)o.gy;
    float ious[3];
    float best = -1.0f; int bn = 0;
    #pragma unroll
    for (int a = 0; a < 3; a++) {
        float aw = c_saw[a], ah = c_sah[a];
        float inter = fmaxf(fminf(o.gw, aw) + 1.0f, 0.0f) *
                      fmaxf(fminf(o.gh, ah) + 1.0f, 0.0f);
        float area_g = (o.gw + 1.0f) * (o.gh + 1.0f);
        float area_a = (aw + 1.0f) * (ah + 1.0f);
        float iou = inter / (area_g + area_a - inter + 1e-16f);
        ious[a] = iou;
        if (iou > best) { best = iou; bn = a; }
    }
    o.iou0 = ious[0]; o.iou1 = ious[1]; o.iou2 = ious[2];
    o.bn = bn;
    o.cls = (int)cl;
}

__device__ __forceinline__ float get_iou(const TgtL& o, int a) {
    return a == 0 ? o.iou0 : (a == 1 ? o.iou1 : o.iou2);
}

__global__ void __launch_bounds__(THREADS)
k_fused(const float* __restrict__ inp,
        const float* __restrict__ tg,
        float* __restrict__ out) {
    __shared__ double s_acc[6];
    __shared__ double s_obj2;
    __shared__ int    s_npos;
    __shared__ float  ws[THREADS / 32];

    const int tid  = threadIdx.x;
    const int lane = tid & 31;
    const int wid  = tid >> 5;

    if (tid < 6) s_acc[tid] = 0.0;
    if (tid == 6) s_obj2 = 0.0;
    if (tid == 7) s_npos = 0;
    __syncthreads();

    // ================= dense conf softplus (all threads) =================
    float dsum = 0.0f;
    {
        int i = blockIdx.x * THREADS + tid;
        #pragma unroll
        for (int r = 0; r < 2; r++) {
            int v = i + r * HALFV;              // < NVEC always (exact tiling)
            int plane = v / VEC_PER_PLANE;      // 0..95
            int off   = (v - plane * VEC_PER_PLANE) * 4;
            int b = plane / AA, a = plane - b * AA;
            const float4* p = (const float4*)(inp +
                ((size_t)(b * CH + a * 25 + 4)) * HWP + off);
            float4 z = *p;
            dsum += sp_fast(z.x) + sp_fast(z.y) + sp_fast(z.z) + sp_fast(z.w);
        }
        #pragma unroll
        for (int o = 16; o > 0; o >>= 1)
            dsum += __shfl_down_sync(0xFFFFFFFFu, dsum, o);
        if (lane == 0) ws[wid] = dsum;
    }

    // ================= sparse: warp-per-target (first 1600 warps) ========
    const int gwarp = blockIdx.x * (THREADS / 32) + wid;
    if (gwarp < BS * TT) {
        const int b = gwarp / TT, t = gwarp % TT;
        TgtL me;
        light_target(tg, b, t, me);
        bool live = me.valid && me.gi >= 0 && me.gi < WW &&
                    me.gj >= 0 && me.gj < HH;          // warp-uniform
        if (live) {
            // in-warp scans over the 50 peer targets of this batch
            bool conflict = false;
            unsigned bits = 0u;
            bool dup0 = false, dup1 = false, dup2 = false;
            #pragma unroll
            for (int r = 0; r < 2; r++) {
                int t2 = lane + r * 32;
                TgtL o; o.valid = false;
                if (t2 < TT) light_target(tg, b, t2, o);
                bool inb = o.valid && o.gi >= 0 && o.gi < WW &&
                           o.gj >= 0 && o.gj < HH;
                bool mc  = inb && (o.gi == me.gi) && (o.gj == me.gj);
                bool mbn = mc && (o.bn == me.bn);
                if (__ballot_sync(0xFFFFFFFFu, mbn && (t2 > t))) conflict = true;
                unsigned bv = mbn ? (1u << o.cls) : 0u;
                #pragma unroll
                for (int s = 16; s > 0; s >>= 1)
                    bv |= __shfl_xor_sync(0xFFFFFFFFu, bv, s);
                bits |= bv;
                if (__ballot_sync(0xFFFFFFFFu, mc && (o.iou0 > 0.5f) && (t2 < t))) dup0 = true;
                if (__ballot_sync(0xFFFFFFFFu, mc && (o.iou1 > 0.5f) && (t2 < t))) dup1 = true;
                if (__ballot_sync(0xFFFFFFFFu, mc && (o.iou2 > 0.5f) && (t2 < t))) dup2 = true;
            }

            float tx = me.gx - (float)me.gi;
            float ty = me.gy - (float)me.gj;
            float v = 0.0f;
            const float* base = inp + ((size_t)(b * CH + me.bn * 25)) * HWP
                                    + me.gj * WW + me.gi;
            if (!conflict && lane < 25) {
                float z = base[(size_t)lane * HWP];
                if (lane == 0) {
                    v = bce_ref(sigmoid_ref(z), tx);
                } else if (lane == 1) {
                    v = bce_ref(sigmoid_ref(z), ty);
                } else if (lane == 2) {
                    float tw = logf(me.gw / c_saw[me.bn] + 1e-16f);
                    float d = z - tw; v = d * d;
                } else if (lane == 3) {
                    float th = logf(me.gh / c_sah[me.bn] + 1e-16f);
                    float d = z - th; v = d * d;
                } else if (lane == 4) {
                    v = -fmaxf(logf(sigmoid_ref(z)), -100.0f);
                } else {
                    float tv = (float)((bits >> (lane - 5)) & 1u);
                    v = bce_ref(sigmoid_ref(z), tv);
                }
            }

            // noobj subtraction: lanes 25..27 handle anchors 0..2
            float nsub = 0.0f;
            {
                int a = lane - 25;
                if (a >= 0 && a < 3) {
                    bool dup = (a == 0) ? dup0 : (a == 1 ? dup1 : dup2);
                    if (get_iou(me, a) > 0.5f && !dup) {
                        float z = inp[((size_t)(b * CH + a * 25 + 4)) * HWP
                                      + me.gj * WW + me.gi];
                        nsub = sp_fast(z);
                    }
                }
            }

            float clsv = (lane >= 5 && lane < 25) ? v : 0.0f;
            #pragma unroll
            for (int s = 16; s > 0; s >>= 1) {
                clsv += __shfl_xor_sync(0xFFFFFFFFu, clsv, s);
                nsub += __shfl_xor_sync(0xFFFFFFFFu, nsub, s);
            }
            float v1 = __shfl_sync(0xFFFFFFFFu, v, 1);
            float v2 = __shfl_sync(0xFFFFFFFFu, v, 2);
            float v3 = __shfl_sync(0xFFFFFFFFu, v, 3);
            float v4 = __shfl_sync(0xFFFFFFFFu, v, 4);

            if (lane == 0) {
                if (nsub != 0.0f) atomicAdd(&s_obj2, -(double)nsub);
                if (!conflict) {
                    atomicAdd(&s_acc[0], (double)v);
                    atomicAdd(&s_acc[1], (double)v1);
                    atomicAdd(&s_acc[2], (double)v2);
                    atomicAdd(&s_acc[3], (double)v3);
                    atomicAdd(&s_acc[4], (double)v4);
                    atomicAdd(&s_acc[5], (double)clsv);
                    atomicAdd(&s_npos, 1);
                }
            }
        }
    }
    __syncthreads();

    // ================= per-block global flush =================
    if (tid == 0) {
        double dtot = 0.0;
        #pragma unroll
        for (int k = 0; k < THREADS / 32; k++) dtot += (double)ws[k];
        atomicAdd(&g_obj2, dtot + s_obj2);
        bool has_sparse = (blockIdx.x * (THREADS / 32)) < BS * TT;
        if (has_sparse) {
            #pragma unroll
            for (int k = 0; k < 6; k++)
                if (s_acc[k] != 0.0) atomicAdd(&g_acc[k], s_acc[k]);
            if (s_npos) atomicAdd(&g_npos, s_npos);
        }
    }

    // ================= last-block finalize =================
    __threadfence();
    __shared__ int s_ticket;
    if (tid == 0) s_ticket = atomicAdd(&g_done, 1);
    __syncthreads();
    if (s_ticket == BLOCKS - 1 && tid == 0) {
        __threadfence();   // acquire: see all blocks' atomics
        const double N = (double)NCELLS;
        double a0 = g_acc[0], a1 = g_acc[1], a2 = g_acc[2];
        double a3 = g_acc[3], a4 = g_acc[4], a5 = g_acc[5];
        double o2 = g_obj2;
        int np = g_npos;
        out[0] = (float)(a0 / N * 2.5);
        out[1] = (float)(a1 / N * 2.5);
        out[2] = (float)(a2 / N * 2.5);
        out[3] = (float)(a3 / N * 2.5);
        out[4] = (float)(a4 / N + 0.5 * o2 / N);
        double dn = (double)np * (double)NC;
        if (dn < 1.0) dn = 1.0;
        out[5] = (float)(a5 / dn);
        // reset for next graph replay
        #pragma unroll
        for (int k = 0; k < 6; k++) g_acc[k] = 0.0;
        g_obj2 = 0.0; g_npos = 0; g_done = 0;
    }
}

extern "C" void kernel_launch(void* const* d_in, const int* in_sizes, int n_in,
                              void* d_out, int out_size) {
    const float* a0 = (const float*)d_in[0];
    const float* a1 = (const float*)d_in[1];
    const float* inp;
    const float* tg;
    if (in_sizes[0] == BS * TT * 5) { tg = a0; inp = a1; }
    else                            { inp = a0; tg = a1; }

    k_fused<<<BLOCKS, THREADS>>>(inp, tg, (float*)d_out);
}